// round 13
// baseline (speedup 1.0000x reference)
#include <cuda_runtime.h>
#include <cstdint>
#include <cstddef>

// Problem constants (fixed by the dataset)
#define B_TOT 4096
#define C_IN  512
#define O_TOT 1024
#define DD    10
#define LL    1024

// Tiling
#define OT        8                  // o's per CTA (one per warp)
#define NB        16                 // b-splits -> grid (16, 128) = 2048 CTAs
                                     // (finer granularity: wave util 77% -> 92%)
#define B_PER_CTA (B_TOT / NB)       // 256 b's per CTA
#define NTHREADS  256
#define BTILE     128                // b's per iteration (lane covers 4)
#define NITER     (B_PER_CTA / BTILE)            // 2
#define ST_PITCH  132                // stage [o][128b]: STS.128 + flush LDS conflict-free
#define W_SM_FLOATS (OT * LL)        // 8192 floats = 32KB staged weights
#define SMEM_FLOATS (W_SM_FLOATS + 2 * OT * ST_PITCH)
#define SMEM_BYTES  (SMEM_FLOATS * 4)

// Scratch: transposed x (xt[c][b]) so per-warp gathers are coalesced lines.
__device__ float g_xt[(size_t)C_IN * B_TOT];
// Repacked thresholds / ordinals (ordinals pre-scaled by B_TOT)
__device__ float4 g_thp[O_TOT * 3];
__device__ int4   g_ordp[O_TOT * 3];

#define TRANS_BLOCKS ((C_IN / 32) * (B_TOT / 32))   // 16*128 = 2048
#define CONV_BLOCKS  48                             // 48*256 = 12288 = O_TOT*12

// Merged prologue: [0,2048) transpose x -> g_xt ; [2048,2096) repack params.
// Transpose tile 32x32, vectorized: 1 LDG.128 + 4 STS + 4 LDS + 1 STG.128
// per thread, all bank-conflict-free.
__global__ void prep_kernel(const float* __restrict__ x,
                            const float* __restrict__ th,
                            const void*  __restrict__ ord_raw) {
    if (blockIdx.x < TRANS_BLOCKS) {
        __shared__ float tt[32 * 33];
        const int tb = blockIdx.x;
        const int cb = tb & (C_IN / 32 - 1);   // channel tile 0..15
        const int bb = tb >> 4;                // b tile 0..127
        const int t = threadIdx.x;
        {
            const int r = t >> 3, q = t & 7;   // row 0..31, float4-col 0..7
            float4 v = *(const float4*)(x + (size_t)(bb * 32 + r) * C_IN
                                          + cb * 32 + 4 * q);
            tt[(4 * q + 0) * 33 + r] = v.x;
            tt[(4 * q + 1) * 33 + r] = v.y;
            tt[(4 * q + 2) * 33 + r] = v.z;
            tt[(4 * q + 3) * 33 + r] = v.w;
        }
        __syncthreads();
        {
            const int c = t >> 3, j = t & 7;   // channel 0..31, float4-col 0..7
            float4 w;
            w.x = tt[c * 33 + 4 * j + 0];
            w.y = tt[c * 33 + 4 * j + 1];
            w.z = tt[c * 33 + 4 * j + 2];
            w.w = tt[c * 33 + 4 * j + 3];
            *(float4*)(g_xt + (size_t)(cb * 32 + c) * B_TOT + bb * 32 + 4 * j) = w;
        }
    } else {
        // Detect ordinals dtype (int64 vs int32) by value-range test.
        __shared__ int is64_s;
        if (threadIdx.x == 0) {
            const long long* p = (const long long*)ord_raw;
            int ok = 1;
            for (int i = 0; i < 16; i++) {
                long long v = p[i];
                if (v < 0 || v >= C_IN) ok = 0;
            }
            is64_s = ok;
        }
        __syncthreads();
        const int use64 = is64_s;
        const long long* p64 = (const long long*)ord_raw;
        const int*       p32 = (const int*)ord_raw;
        float* thf = (float*)g_thp;
        int*   odf = (int*)g_ordp;
        int j = (blockIdx.x - TRANS_BLOCKS) * blockDim.x + threadIdx.x;
        if (j < O_TOT * 12) {
            int o = j / 12, k = j % 12;
            float tv = 0.0f;
            int   ov = 0;
            if (k < DD) {
                tv = th[o * DD + k];
                ov = (use64 ? (int)p64[o * DD + k] : p32[o * DD + k]) * B_TOT;
            }
            thf[j] = tv;
            odf[j] = ov;
        }
    }
}

// occ 3: 85-reg budget fits the ~80-reg live set (10 float4 loads + params).
__global__ __launch_bounds__(NTHREADS, 3)
void fern_kernel(const float* __restrict__ wts, float* __restrict__ out) {
    extern __shared__ float sm[];
    float* wsm   = sm;                  // [OT][LL] staged weights (32KB)
    float* stage = sm + W_SM_FLOATS;    // [2][OT][ST_PITCH] ping-pong stage

    const int tid  = threadIdx.x;
    const int lane = tid & 31;
    const int warp = tid >> 5;          // o within CTA (fixed)
    const int o_begin = blockIdx.y * OT;
    const int bbase   = blockIdx.x * B_PER_CTA;

    // Stage weights [o_begin : o_begin+8] into smem. 2048 float4 / 256 thr = 8 each.
    {
        const float4* src = (const float4*)(wts + (size_t)o_begin * LL);
        float4* dst = (float4*)wsm;
        #pragma unroll
        for (int i = 0; i < W_SM_FLOATS / 4 / NTHREADS; i++)
            dst[tid + i * NTHREADS] = src[tid + i * NTHREADS];
    }

    // Per-warp params, loaded ONCE (o fixed for entire CTA lifetime).
    const int o = o_begin + warp;
    const float4 t0 = g_thp[o * 3 + 0];
    const float4 t1 = g_thp[o * 3 + 1];
    const float4 t2 = g_thp[o * 3 + 2];
    const int4   c0 = g_ordp[o * 3 + 0];
    const int4   c1 = g_ordp[o * 3 + 1];
    const int4   c2 = g_ordp[o * 3 + 2];

    // 10 float4 base pointers: each lane covers b = 4*lane .. 4*lane+3.
    const float* xf = g_xt + bbase;
    const float4* xp0 = (const float4*)(xf + c0.x) + lane;
    const float4* xp1 = (const float4*)(xf + c0.y) + lane;
    const float4* xp2 = (const float4*)(xf + c0.z) + lane;
    const float4* xp3 = (const float4*)(xf + c0.w) + lane;
    const float4* xp4 = (const float4*)(xf + c1.x) + lane;
    const float4* xp5 = (const float4*)(xf + c1.y) + lane;
    const float4* xp6 = (const float4*)(xf + c1.z) + lane;
    const float4* xp7 = (const float4*)(xf + c1.w) + lane;
    const float4* xp8 = (const float4*)(xf + c2.x) + lane;
    const float4* xp9 = (const float4*)(xf + c2.y) + lane;
    const float* wrow = wsm + (warp << 10);

    __syncthreads();   // weights staged

    #pragma unroll
    for (int itp = 0; itp < NITER; itp++) {              // 2 iterations
        float* sbuf = stage + (itp & 1) * (OT * ST_PITCH);
        const int off = itp * 32;                        // float4 elements

        // 10 independent coalesced LDG.128 in flight (128 b's this iter).
        float4 v0 = xp0[off];
        float4 v1 = xp1[off];
        float4 v2 = xp2[off];
        float4 v3 = xp3[off];
        float4 v4 = xp4[off];
        float4 v5 = xp5[off];
        float4 v6 = xp6[off];
        float4 v7 = xp7[off];
        float4 v8 = xp8[off];
        float4 v9 = xp9[off];

        float4 res;
        #define COMPONENT(F, RR)                                            \
        {                                                                   \
            float m0 = v0.F - t0.x, m1 = v1.F - t0.y, m2 = v2.F - t0.z;     \
            float m3 = v3.F - t0.w, m4 = v4.F - t1.x, m5 = v5.F - t1.y;     \
            float m6 = v6.F - t1.z, m7 = v7.F - t1.w, m8 = v8.F - t2.x;     \
            float m9 = v9.F - t2.y;                                         \
            int leaf = ((m0 > 0.0f) << 9) | ((m1 > 0.0f) << 8) |            \
                       ((m2 > 0.0f) << 7) | ((m3 > 0.0f) << 6) |            \
                       ((m4 > 0.0f) << 5) | ((m5 > 0.0f) << 4) |            \
                       ((m6 > 0.0f) << 3) | ((m7 > 0.0f) << 2) |            \
                       ((m8 > 0.0f) << 1) |  (m9 > 0.0f);                   \
            float mn = fminf(                                               \
                fminf(fminf(fminf(fabsf(m0), fabsf(m1)),                    \
                            fminf(fabsf(m2), fabsf(m3))),                   \
                      fminf(fminf(fabsf(m4), fabsf(m5)),                    \
                            fminf(fabsf(m6), fabsf(m7)))),                  \
                fminf(fabsf(m8), fabsf(m9)));                               \
            RR = wrow[leaf] * mn;                                           \
        }
        COMPONENT(x, res.x)
        COMPONENT(y, res.y)
        COMPONENT(z, res.z)
        COMPONENT(w, res.w)
        #undef COMPONENT

        // Stage [o][b]: one STS.128, conflict-free, 16B aligned (528w + 16l).
        *(float4*)&sbuf[warp * ST_PITCH + 4 * lane] = res;
        __syncthreads();

        // Flush 128 b x 8 o; 4 elements/thread.
        // LDS banks: exact 32-bank cover; STG: 32B coalesced segments.
        {
            const int bl = tid >> 3, oo = tid & 7;       // bl 0..31, oo 0..7
            const int bg = bbase + itp * BTILE;
            #pragma unroll
            for (int m = 0; m < 4; m++)
                out[(size_t)(bg + bl + 32 * m) * O_TOT + o_begin + oo] =
                    sbuf[oo * ST_PITCH + bl + 32 * m];
        }
        // Ping-pong: next iteration writes the other buffer; its barrier
        // orders reuse of this one.
    }
}

extern "C" void kernel_launch(void* const* d_in, const int* in_sizes, int n_in,
                              void* d_out, int out_size) {
    (void)in_sizes; (void)n_in; (void)out_size;
    const float* x   = (const float*)d_in[0];
    const float* th  = (const float*)d_in[1];
    const void*  ord = d_in[2];
    const float* wts = (const float*)d_in[3];
    float* out = (float*)d_out;

    prep_kernel<<<TRANS_BLOCKS + CONV_BLOCKS, 256>>>(x, th, ord);

    cudaFuncSetAttribute(fern_kernel,
                         cudaFuncAttributeMaxDynamicSharedMemorySize, SMEM_BYTES);
    dim3 grid(NB, O_TOT / OT);   // (16, 128)
    fern_kernel<<<grid, NTHREADS, SMEM_BYTES>>>(wts, out);
}

// round 14
// speedup vs baseline: 1.1013x; 1.1013x over previous
#include <cuda_runtime.h>
#include <cstdint>
#include <cstddef>

// Problem constants (fixed by the dataset)
#define B_TOT 4096
#define C_IN  512
#define O_TOT 1024
#define DD    10
#define LL    1024

// Tiling
#define OT        8                  // o's per CTA (one per warp)
#define NB        8                  // b-splits -> grid (8, 128); NB=16 measured WORSE
                                     // (per-CTA staging cost doubles, R13)
#define B_PER_CTA (B_TOT / NB)       // 512 b's per CTA
#define NTHREADS  256
#define ST_PITCH  68                 // stage [o][64 b] pitch: STS.64 + flush LDS conflict-free
#define W_SM_FLOATS (OT * LL)        // 8192 floats = 32KB staged weights
#define SMEM_FLOATS (W_SM_FLOATS + 2 * OT * ST_PITCH)
#define SMEM_BYTES  (SMEM_FLOATS * 4)

// Scratch: transposed x (xt[c][b]) so per-warp gathers are coalesced lines.
__device__ float g_xt[(size_t)C_IN * B_TOT];
// Repacked thresholds / ordinals (ordinals pre-scaled by B_TOT)
__device__ float4 g_thp[O_TOT * 3];
__device__ int4   g_ordp[O_TOT * 3];

#define TRANS_BLOCKS ((C_IN / 32) * (B_TOT / 32))   // 16*128 = 2048
#define CONV_BLOCKS  48                             // 48*256 = 12288 = O_TOT*12

// Merged prologue: [0,2048) transpose x -> g_xt ; [2048,2096) repack params.
// Transpose tile 32x32, vectorized: 1 LDG.128 + 4 STS + 4 LDS + 1 STG.128
// per thread, all bank-conflict-free (verified R11).
__global__ void prep_kernel(const float* __restrict__ x,
                            const float* __restrict__ th,
                            const void*  __restrict__ ord_raw) {
    if (blockIdx.x < TRANS_BLOCKS) {
        __shared__ float tt[32 * 33];
        const int tb = blockIdx.x;
        const int cb = tb & (C_IN / 32 - 1);   // channel tile 0..15
        const int bb = tb >> 4;                // b tile 0..127
        const int t = threadIdx.x;
        {
            const int r = t >> 3, q = t & 7;   // row 0..31, float4-col 0..7
            float4 v = *(const float4*)(x + (size_t)(bb * 32 + r) * C_IN
                                          + cb * 32 + 4 * q);
            tt[(4 * q + 0) * 33 + r] = v.x;
            tt[(4 * q + 1) * 33 + r] = v.y;
            tt[(4 * q + 2) * 33 + r] = v.z;
            tt[(4 * q + 3) * 33 + r] = v.w;
        }
        __syncthreads();
        {
            const int c = t >> 3, j = t & 7;   // channel 0..31, float4-col 0..7
            float4 w;
            w.x = tt[c * 33 + 4 * j + 0];
            w.y = tt[c * 33 + 4 * j + 1];
            w.z = tt[c * 33 + 4 * j + 2];
            w.w = tt[c * 33 + 4 * j + 3];
            *(float4*)(g_xt + (size_t)(cb * 32 + c) * B_TOT + bb * 32 + 4 * j) = w;
        }
    } else {
        // Detect ordinals dtype (int64 vs int32) by value-range test.
        __shared__ int is64_s;
        if (threadIdx.x == 0) {
            const long long* p = (const long long*)ord_raw;
            int ok = 1;
            for (int i = 0; i < 16; i++) {
                long long v = p[i];
                if (v < 0 || v >= C_IN) ok = 0;
            }
            is64_s = ok;
        }
        __syncthreads();
        const int use64 = is64_s;
        const long long* p64 = (const long long*)ord_raw;
        const int*       p32 = (const int*)ord_raw;
        float* thf = (float*)g_thp;
        int*   odf = (int*)g_ordp;
        int j = (blockIdx.x - TRANS_BLOCKS) * blockDim.x + threadIdx.x;
        if (j < O_TOT * 12) {
            int o = j / 12, k = j % 12;
            float tv = 0.0f;
            int   ov = 0;
            if (k < DD) {
                tv = th[o * DD + k];
                ov = (use64 ? (int)p64[o * DD + k] : p32[o * DD + k]) * B_TOT;
            }
            thf[j] = tv;
            odf[j] = ov;
        }
    }
}

// occ 3 (85-reg budget): fits the double-buffered live set (20 float2 loads
// + params + pointers). A tighter cap collapses MLP (R6); occ 4 without
// prefetch is slower (R8).
__global__ __launch_bounds__(NTHREADS, 3)
void fern_kernel(const float* __restrict__ wts, float* __restrict__ out) {
    extern __shared__ float sm[];
    float* wsm   = sm;                  // [OT][LL] staged weights (32KB)
    float* stage = sm + W_SM_FLOATS;    // [2][OT][ST_PITCH] ping-pong stage

    const int tid  = threadIdx.x;
    const int lane = tid & 31;
    const int warp = tid >> 5;          // o within CTA (fixed)
    const int o_begin = blockIdx.y * OT;
    const int bbase   = blockIdx.x * B_PER_CTA;

    // Stage weights [o_begin : o_begin+8] into smem. 2048 float4 / 256 thr = 8 each.
    {
        const float4* src = (const float4*)(wts + (size_t)o_begin * LL);
        float4* dst = (float4*)wsm;
        #pragma unroll
        for (int i = 0; i < W_SM_FLOATS / 4 / NTHREADS; i++)
            dst[tid + i * NTHREADS] = src[tid + i * NTHREADS];
    }

    // Per-warp params, loaded ONCE (o fixed for entire CTA lifetime).
    const int o = o_begin + warp;
    const float4 t0 = g_thp[o * 3 + 0];
    const float4 t1 = g_thp[o * 3 + 1];
    const float4 t2 = g_thp[o * 3 + 2];
    const int4   c0 = g_ordp[o * 3 + 0];
    const int4   c1 = g_ordp[o * 3 + 1];
    const int4   c2 = g_ordp[o * 3 + 2];

    // 10 float2 base pointers: each lane covers b = 2*lane, 2*lane+1.
    const float* xf = g_xt + bbase;
    const float2* xp0 = (const float2*)(xf + c0.x) + lane;
    const float2* xp1 = (const float2*)(xf + c0.y) + lane;
    const float2* xp2 = (const float2*)(xf + c0.z) + lane;
    const float2* xp3 = (const float2*)(xf + c0.w) + lane;
    const float2* xp4 = (const float2*)(xf + c1.x) + lane;
    const float2* xp5 = (const float2*)(xf + c1.y) + lane;
    const float2* xp6 = (const float2*)(xf + c1.z) + lane;
    const float2* xp7 = (const float2*)(xf + c1.w) + lane;
    const float2* xp8 = (const float2*)(xf + c2.x) + lane;
    const float2* xp9 = (const float2*)(xf + c2.y) + lane;
    const float* wrow = wsm + (warp << 10);

    __syncthreads();   // weights staged

    // Software pipeline: prefetch tile 0, then each iteration prefetches
    // tile itp+1 BEFORE consuming tile itp (20 LDG.64 in flight).
    float2 v0 = xp0[0], v1 = xp1[0], v2 = xp2[0], v3 = xp3[0], v4 = xp4[0];
    float2 v5 = xp5[0], v6 = xp6[0], v7 = xp7[0], v8 = xp8[0], v9 = xp9[0];

    #pragma unroll
    for (int itp = 0; itp < B_PER_CTA / 64; itp++) {     // 8 iterations
        float* sbuf = stage + (itp & 1) * (OT * ST_PITCH);

        // Prefetch next tile (overlaps all math/smem/barrier/flush below).
        float2 n0, n1, n2, n3, n4, n5, n6, n7, n8, n9;
        if (itp < B_PER_CTA / 64 - 1) {
            const int noff = (itp + 1) * 32;             // float2 elements
            n0 = xp0[noff]; n1 = xp1[noff]; n2 = xp2[noff]; n3 = xp3[noff];
            n4 = xp4[noff]; n5 = xp5[noff]; n6 = xp6[noff]; n7 = xp7[noff];
            n8 = xp8[noff]; n9 = xp9[noff];
        }

        float r0, r1;
        {   // b = 2*lane  (.x components)
            float m0 = v0.x - t0.x, m1 = v1.x - t0.y, m2 = v2.x - t0.z;
            float m3 = v3.x - t0.w, m4 = v4.x - t1.x, m5 = v5.x - t1.y;
            float m6 = v6.x - t1.z, m7 = v7.x - t1.w, m8 = v8.x - t2.x;
            float m9 = v9.x - t2.y;
            int leaf = ((m0 > 0.0f) << 9) | ((m1 > 0.0f) << 8) |
                       ((m2 > 0.0f) << 7) | ((m3 > 0.0f) << 6) |
                       ((m4 > 0.0f) << 5) | ((m5 > 0.0f) << 4) |
                       ((m6 > 0.0f) << 3) | ((m7 > 0.0f) << 2) |
                       ((m8 > 0.0f) << 1) |  (m9 > 0.0f);
            float mn = fminf(
                fminf(fminf(fminf(fabsf(m0), fabsf(m1)), fminf(fabsf(m2), fabsf(m3))),
                      fminf(fminf(fabsf(m4), fabsf(m5)), fminf(fabsf(m6), fabsf(m7)))),
                fminf(fabsf(m8), fabsf(m9)));
            r0 = wrow[leaf] * mn;
        }
        {   // b = 2*lane + 1  (.y components)
            float m0 = v0.y - t0.x, m1 = v1.y - t0.y, m2 = v2.y - t0.z;
            float m3 = v3.y - t0.w, m4 = v4.y - t1.x, m5 = v5.y - t1.y;
            float m6 = v6.y - t1.z, m7 = v7.y - t1.w, m8 = v8.y - t2.x;
            float m9 = v9.y - t2.y;
            int leaf = ((m0 > 0.0f) << 9) | ((m1 > 0.0f) << 8) |
                       ((m2 > 0.0f) << 7) | ((m3 > 0.0f) << 6) |
                       ((m4 > 0.0f) << 5) | ((m5 > 0.0f) << 4) |
                       ((m6 > 0.0f) << 3) | ((m7 > 0.0f) << 2) |
                       ((m8 > 0.0f) << 1) |  (m9 > 0.0f);
            float mn = fminf(
                fminf(fminf(fminf(fabsf(m0), fabsf(m1)), fminf(fabsf(m2), fabsf(m3))),
                      fminf(fminf(fabsf(m4), fabsf(m5)), fminf(fabsf(m6), fabsf(m7)))),
                fminf(fabsf(m8), fabsf(m9)));
            r1 = wrow[leaf] * mn;
        }

        // Stage [o][b]: STS.64 consecutive within the warp -> conflict-free.
        *(float2*)&sbuf[warp * ST_PITCH + 2 * lane] = make_float2(r0, r1);
        __syncthreads();

        // Flush 64 b x 8 o; 2 elements/thread, 32B coalesced STG segments.
        // LDS banks (4*oo + bl) mod 32, bl in {4w..4w+3}: exact 32-bank cover.
        {
            const int bl = tid >> 3, oo = tid & 7;       // bl 0..31, oo 0..7
            const int bg = bbase + itp * 64;
            out[(size_t)(bg + bl) * O_TOT + o_begin + oo] =
                sbuf[oo * ST_PITCH + bl];
            out[(size_t)(bg + bl + 32) * O_TOT + o_begin + oo] =
                sbuf[oo * ST_PITCH + bl + 32];
        }
        // Ping-pong: next iteration writes the other buffer; its barrier
        // orders reuse of this one.

        // Rotate pipeline registers (fully unrolled -> pure renaming).
        v0 = n0; v1 = n1; v2 = n2; v3 = n3; v4 = n4;
        v5 = n5; v6 = n6; v7 = n7; v8 = n8; v9 = n9;
    }
}

extern "C" void kernel_launch(void* const* d_in, const int* in_sizes, int n_in,
                              void* d_out, int out_size) {
    (void)in_sizes; (void)n_in; (void)out_size;
    const float* x   = (const float*)d_in[0];
    const float* th  = (const float*)d_in[1];
    const void*  ord = d_in[2];
    const float* wts = (const float*)d_in[3];
    float* out = (float*)d_out;

    prep_kernel<<<TRANS_BLOCKS + CONV_BLOCKS, 256>>>(x, th, ord);

    cudaFuncSetAttribute(fern_kernel,
                         cudaFuncAttributeMaxDynamicSharedMemorySize, SMEM_BYTES);
    dim3 grid(NB, O_TOT / OT);   // (8, 128)
    fern_kernel<<<grid, NTHREADS, SMEM_BYTES>>>(wts, out);
}

// round 15
// speedup vs baseline: 1.1027x; 1.0013x over previous
#include <cuda_runtime.h>
#include <cstdint>
#include <cstddef>

// Problem constants (fixed by the dataset)
#define B_TOT 4096
#define C_IN  512
#define O_TOT 1024
#define DD    10
#define LL    1024

// Tiling
#define OT        8                  // o's per CTA (one per warp)
#define NB        8                  // b-splits -> grid (8, 128); NB=16 measured WORSE (R13)
#define B_PER_CTA (B_TOT / NB)       // 512 b's per CTA
#define NTHREADS  256
#define ST_PITCH  68                 // stage [o][64 b] pitch: STS.64 + flush LDS conflict-free
#define W_SM_FLOATS (OT * LL)        // 8192 floats = 32KB staged weights
#define SMEM_FLOATS (W_SM_FLOATS + 2 * OT * ST_PITCH)
#define SMEM_BYTES  (SMEM_FLOATS * 4)

// Scratch: transposed x (xt[c][b]) so per-warp gathers are coalesced lines.
__device__ float g_xt[(size_t)C_IN * B_TOT];
// Repacked thresholds / ordinals (ordinals pre-scaled by B_TOT)
__device__ float4 g_thp[O_TOT * 3];
__device__ int4   g_ordp[O_TOT * 3];

// Fat transpose blocks: each handles a 32b x 128c slab (4 of the 32x32 tiles).
#define TRANS_BLOCKS ((C_IN / 128) * (B_TOT / 32))  // 4*128 = 512
#define CONV_BLOCKS  48                             // 48*256 = 12288 = O_TOT*12

// Merged prologue: [0,512) transpose x -> g_xt ; [512,560) repack params.
// Per thread: 4 LDG.128 (independent, MLP=4) + 16 STS + 16 LDS + 4 STG.128,
// all bank-conflict-free (same 32x33 tile pattern as before, x4 buffers).
__global__ void prep_kernel(const float* __restrict__ x,
                            const float* __restrict__ th,
                            const void*  __restrict__ ord_raw) {
    if (blockIdx.x < TRANS_BLOCKS) {
        __shared__ float tt[4][32 * 33];
        const int tb = blockIdx.x;
        const int cb = tb & (C_IN / 128 - 1);  // 128-channel slab 0..3
        const int bb = tb >> 2;                // b tile 0..127
        const int t = threadIdx.x;
        {
            const int r = t >> 3, q = t & 7;   // row 0..31, float4-col 0..7
            const float* xrow = x + (size_t)(bb * 32 + r) * C_IN + cb * 128 + 4 * q;
            #pragma unroll
            for (int k = 0; k < 4; k++) {      // 4 independent LDG.128
                float4 v = *(const float4*)(xrow + k * 32);
                tt[k][(4 * q + 0) * 33 + r] = v.x;
                tt[k][(4 * q + 1) * 33 + r] = v.y;
                tt[k][(4 * q + 2) * 33 + r] = v.z;
                tt[k][(4 * q + 3) * 33 + r] = v.w;
            }
        }
        __syncthreads();
        {
            const int c = t >> 3, j = t & 7;   // channel 0..31, float4-col 0..7
            #pragma unroll
            for (int k = 0; k < 4; k++) {
                float4 w;
                w.x = tt[k][c * 33 + 4 * j + 0];
                w.y = tt[k][c * 33 + 4 * j + 1];
                w.z = tt[k][c * 33 + 4 * j + 2];
                w.w = tt[k][c * 33 + 4 * j + 3];
                *(float4*)(g_xt + (size_t)(cb * 128 + k * 32 + c) * B_TOT
                                 + bb * 32 + 4 * j) = w;
            }
        }
    } else {
        // Detect ordinals dtype (int64 vs int32) by value-range test.
        __shared__ int is64_s;
        if (threadIdx.x == 0) {
            const long long* p = (const long long*)ord_raw;
            int ok = 1;
            for (int i = 0; i < 16; i++) {
                long long v = p[i];
                if (v < 0 || v >= C_IN) ok = 0;
            }
            is64_s = ok;
        }
        __syncthreads();
        const int use64 = is64_s;
        const long long* p64 = (const long long*)ord_raw;
        const int*       p32 = (const int*)ord_raw;
        float* thf = (float*)g_thp;
        int*   odf = (int*)g_ordp;
        int j = (blockIdx.x - TRANS_BLOCKS) * blockDim.x + threadIdx.x;
        if (j < O_TOT * 12) {
            int o = j / 12, k = j % 12;
            float tv = 0.0f;
            int   ov = 0;
            if (k < DD) {
                tv = th[o * DD + k];
                ov = (use64 ? (int)p64[o * DD + k] : p32[o * DD + k]) * B_TOT;
            }
            thf[j] = tv;
            odf[j] = ov;
        }
    }
}

// occ 3 (85-reg budget): fits the double-buffered live set (20 float2 loads
// + params + pointers). A tighter cap collapses MLP (R6); occ 4 without
// prefetch is slower (R8). FERN IDENTICAL TO R14 (best measured: 19.97us).
__global__ __launch_bounds__(NTHREADS, 3)
void fern_kernel(const float* __restrict__ wts, float* __restrict__ out) {
    extern __shared__ float sm[];
    float* wsm   = sm;                  // [OT][LL] staged weights (32KB)
    float* stage = sm + W_SM_FLOATS;    // [2][OT][ST_PITCH] ping-pong stage

    const int tid  = threadIdx.x;
    const int lane = tid & 31;
    const int warp = tid >> 5;          // o within CTA (fixed)
    const int o_begin = blockIdx.y * OT;
    const int bbase   = blockIdx.x * B_PER_CTA;

    // Stage weights [o_begin : o_begin+8] into smem. 2048 float4 / 256 thr = 8 each.
    {
        const float4* src = (const float4*)(wts + (size_t)o_begin * LL);
        float4* dst = (float4*)wsm;
        #pragma unroll
        for (int i = 0; i < W_SM_FLOATS / 4 / NTHREADS; i++)
            dst[tid + i * NTHREADS] = src[tid + i * NTHREADS];
    }

    // Per-warp params, loaded ONCE (o fixed for entire CTA lifetime).
    const int o = o_begin + warp;
    const float4 t0 = g_thp[o * 3 + 0];
    const float4 t1 = g_thp[o * 3 + 1];
    const float4 t2 = g_thp[o * 3 + 2];
    const int4   c0 = g_ordp[o * 3 + 0];
    const int4   c1 = g_ordp[o * 3 + 1];
    const int4   c2 = g_ordp[o * 3 + 2];

    // 10 float2 base pointers: each lane covers b = 2*lane, 2*lane+1.
    const float* xf = g_xt + bbase;
    const float2* xp0 = (const float2*)(xf + c0.x) + lane;
    const float2* xp1 = (const float2*)(xf + c0.y) + lane;
    const float2* xp2 = (const float2*)(xf + c0.z) + lane;
    const float2* xp3 = (const float2*)(xf + c0.w) + lane;
    const float2* xp4 = (const float2*)(xf + c1.x) + lane;
    const float2* xp5 = (const float2*)(xf + c1.y) + lane;
    const float2* xp6 = (const float2*)(xf + c1.z) + lane;
    const float2* xp7 = (const float2*)(xf + c1.w) + lane;
    const float2* xp8 = (const float2*)(xf + c2.x) + lane;
    const float2* xp9 = (const float2*)(xf + c2.y) + lane;
    const float* wrow = wsm + (warp << 10);

    __syncthreads();   // weights staged

    // Software pipeline: prefetch tile 0, then each iteration prefetches
    // tile itp+1 BEFORE consuming tile itp (20 LDG.64 in flight).
    float2 v0 = xp0[0], v1 = xp1[0], v2 = xp2[0], v3 = xp3[0], v4 = xp4[0];
    float2 v5 = xp5[0], v6 = xp6[0], v7 = xp7[0], v8 = xp8[0], v9 = xp9[0];

    #pragma unroll
    for (int itp = 0; itp < B_PER_CTA / 64; itp++) {     // 8 iterations
        float* sbuf = stage + (itp & 1) * (OT * ST_PITCH);

        // Prefetch next tile (overlaps all math/smem/barrier/flush below).
        float2 n0, n1, n2, n3, n4, n5, n6, n7, n8, n9;
        if (itp < B_PER_CTA / 64 - 1) {
            const int noff = (itp + 1) * 32;             // float2 elements
            n0 = xp0[noff]; n1 = xp1[noff]; n2 = xp2[noff]; n3 = xp3[noff];
            n4 = xp4[noff]; n5 = xp5[noff]; n6 = xp6[noff]; n7 = xp7[noff];
            n8 = xp8[noff]; n9 = xp9[noff];
        }

        float r0, r1;
        {   // b = 2*lane  (.x components)
            float m0 = v0.x - t0.x, m1 = v1.x - t0.y, m2 = v2.x - t0.z;
            float m3 = v3.x - t0.w, m4 = v4.x - t1.x, m5 = v5.x - t1.y;
            float m6 = v6.x - t1.z, m7 = v7.x - t1.w, m8 = v8.x - t2.x;
            float m9 = v9.x - t2.y;
            int leaf = ((m0 > 0.0f) << 9) | ((m1 > 0.0f) << 8) |
                       ((m2 > 0.0f) << 7) | ((m3 > 0.0f) << 6) |
                       ((m4 > 0.0f) << 5) | ((m5 > 0.0f) << 4) |
                       ((m6 > 0.0f) << 3) | ((m7 > 0.0f) << 2) |
                       ((m8 > 0.0f) << 1) |  (m9 > 0.0f);
            float mn = fminf(
                fminf(fminf(fminf(fabsf(m0), fabsf(m1)), fminf(fabsf(m2), fabsf(m3))),
                      fminf(fminf(fabsf(m4), fabsf(m5)), fminf(fabsf(m6), fabsf(m7)))),
                fminf(fabsf(m8), fabsf(m9)));
            r0 = wrow[leaf] * mn;
        }
        {   // b = 2*lane + 1  (.y components)
            float m0 = v0.y - t0.x, m1 = v1.y - t0.y, m2 = v2.y - t0.z;
            float m3 = v3.y - t0.w, m4 = v4.y - t1.x, m5 = v5.y - t1.y;
            float m6 = v6.y - t1.z, m7 = v7.y - t1.w, m8 = v8.y - t2.x;
            float m9 = v9.y - t2.y;
            int leaf = ((m0 > 0.0f) << 9) | ((m1 > 0.0f) << 8) |
                       ((m2 > 0.0f) << 7) | ((m3 > 0.0f) << 6) |
                       ((m4 > 0.0f) << 5) | ((m5 > 0.0f) << 4) |
                       ((m6 > 0.0f) << 3) | ((m7 > 0.0f) << 2) |
                       ((m8 > 0.0f) << 1) |  (m9 > 0.0f);
            float mn = fminf(
                fminf(fminf(fminf(fabsf(m0), fabsf(m1)), fminf(fabsf(m2), fabsf(m3))),
                      fminf(fminf(fabsf(m4), fabsf(m5)), fminf(fabsf(m6), fabsf(m7)))),
                fminf(fabsf(m8), fabsf(m9)));
            r1 = wrow[leaf] * mn;
        }

        // Stage [o][b]: STS.64 consecutive within the warp -> conflict-free.
        *(float2*)&sbuf[warp * ST_PITCH + 2 * lane] = make_float2(r0, r1);
        __syncthreads();

        // Flush 64 b x 8 o; 2 elements/thread, 32B coalesced STG segments.
        // LDS banks (4*oo + bl) mod 32, bl in {4w..4w+3}: exact 32-bank cover.
        {
            const int bl = tid >> 3, oo = tid & 7;       // bl 0..31, oo 0..7
            const int bg = bbase + itp * 64;
            out[(size_t)(bg + bl) * O_TOT + o_begin + oo] =
                sbuf[oo * ST_PITCH + bl];
            out[(size_t)(bg + bl + 32) * O_TOT + o_begin + oo] =
                sbuf[oo * ST_PITCH + bl + 32];
        }
        // Ping-pong: next iteration writes the other buffer; its barrier
        // orders reuse of this one.

        // Rotate pipeline registers (fully unrolled -> pure renaming).
        v0 = n0; v1 = n1; v2 = n2; v3 = n3; v4 = n4;
        v5 = n5; v6 = n6; v7 = n7; v8 = n8; v9 = n9;
    }
}

extern "C" void kernel_launch(void* const* d_in, const int* in_sizes, int n_in,
                              void* d_out, int out_size) {
    (void)in_sizes; (void)n_in; (void)out_size;
    const float* x   = (const float*)d_in[0];
    const float* th  = (const float*)d_in[1];
    const void*  ord = d_in[2];
    const float* wts = (const float*)d_in[3];
    float* out = (float*)d_out;

    prep_kernel<<<TRANS_BLOCKS + CONV_BLOCKS, 256>>>(x, th, ord);

    cudaFuncSetAttribute(fern_kernel,
                         cudaFuncAttributeMaxDynamicSharedMemorySize, SMEM_BYTES);
    dim3 grid(NB, O_TOT / OT);   // (8, 128)
    fern_kernel<<<grid, NTHREADS, SMEM_BYTES>>>(wts, out);
}